// round 15
// baseline (speedup 1.0000x reference)
#include <cuda_runtime.h>
#include <cstdint>

// INT8BertEmbeddings R15 (= R14 resubmit; R14 hit the recurring broker
// infra failure). R13 + cross-token register prefetch of the word gather:
// token i+1's 6 LDG.128s issue before token i's reduction chain and are
// consumed next iteration (true register destinations, unlike R8's
// hint-only prefetch). Cost +24 regs (occ ~37%), bounded at ~1.4us by the
// R11/R12 A/B, vs predicted 4-6us latency-overlap gain.
// Single kernel, s-major CTA mapping, pt+ln in smem (R13 wins kept).

constexpr int H    = 768;
constexpr int VPR  = H / 4;      // 192 float4/int4 per row
constexpr int TPB  = 128;        // 4 warps
constexpr int NW   = TPB / 32;
constexpr int TOKW = 4;          // batches per warp
constexpr int BPC  = NW * TOKW;  // 16 batches per CTA
constexpr int CH   = VPR / 32;   // 6 chunks per warp per row
constexpr int MAX_T = 2;

__device__ __forceinline__ void store_streaming(float4* addr, float4 v) {
    asm volatile("st.global.cs.v4.f32 [%0], {%1, %2, %3, %4};"
                 :: "l"(addr), "f"(v.x), "f"(v.y), "f"(v.z), "f"(v.w)
                 : "memory");
}

__global__ __launch_bounds__(TPB, 6) void bert_emb_ln_kernel(
    const int*  __restrict__ input_ids,
    const int*  __restrict__ token_type_ids,
    const int4* __restrict__ word_table,
    const float* __restrict__ word_scale,
    const int4* __restrict__ pos_table,
    const float* __restrict__ pos_scale,
    const int4* __restrict__ type_table,
    const float* __restrict__ type_scale,
    const float4* __restrict__ ln_w,
    const float4* __restrict__ ln_b,
    float4* __restrict__ out,
    int S, int B)
{
    const int tid  = threadIdx.x;
    const int lane = tid & 31;
    const int warp = tid >> 5;

    const int s  = blockIdx.x % S;           // sequence position for this CTA
    const int bg = blockIdx.x / S;           // batch group
    const int b0 = bg * BPC + warp * TOKW;   // first batch for this warp

    // smem: fused pos+type rows for this s (both type variants) + ln params.
    __shared__ __align__(16) float4 s_pt[MAX_T][VPR];
    __shared__ __align__(16) float4 s_g[VPR];
    __shared__ __align__(16) float4 s_b[VPR];

    {
        const float ps = __ldg(pos_scale);
        const float ts = __ldg(type_scale);
        #pragma unroll
        for (int c = 0; c < (VPR + TPB - 1) / TPB; ++c) {
            const int idx = c * TPB + tid;
            if (idx < VPR) {
                const int4 pr = __ldg(&pos_table[(size_t)s * VPR + idx]);
                const int4 t0 = __ldg(&type_table[idx]);
                const int4 t1 = __ldg(&type_table[VPR + idx]);
                const float px = (float)pr.x * ps, py = (float)pr.y * ps;
                const float pz = (float)pr.z * ps, pw = (float)pr.w * ps;
                s_pt[0][idx] = make_float4(px + (float)t0.x * ts, py + (float)t0.y * ts,
                                           pz + (float)t0.z * ts, pw + (float)t0.w * ts);
                s_pt[1][idx] = make_float4(px + (float)t1.x * ts, py + (float)t1.y * ts,
                                           pz + (float)t1.z * ts, pw + (float)t1.w * ts);
                s_g[idx] = __ldg(&ln_w[idx]);
                s_b[idx] = __ldg(&ln_b[idx]);
            }
        }
    }
    __syncthreads();   // uniform, once

    const float ws = __ldg(word_scale);

    // Prefetch token 0's word row + type id.
    int4 wcur[CH];
    int  trow_cur = 0;
    if (b0 < B) {
        const int token0 = b0 * S + s;
        const int wrow   = __ldg(&input_ids[token0]);
        trow_cur = __ldg(&token_type_ids[token0]);
        const int4* wp = word_table + (size_t)wrow * VPR;
        #pragma unroll
        for (int c = 0; c < CH; ++c) wcur[c] = __ldg(&wp[c * 32 + lane]);
    }

    #pragma unroll
    for (int i = 0; i < TOKW; ++i) {
        const int b = b0 + i;
        if (b >= B) return;
        const int token = b * S + s;

        // Issue next token's gathers BEFORE this token's reduction chain.
        int4 wnxt[CH];
        int  trow_nxt = 0;
        const bool have_next = (i + 1 < TOKW) && (b + 1 < B);
        if (have_next) {
            const int tn   = (b + 1) * S + s;
            const int wrow = __ldg(&input_ids[tn]);
            trow_nxt = __ldg(&token_type_ids[tn]);
            const int4* wp = word_table + (size_t)wrow * VPR;
            #pragma unroll
            for (int c = 0; c < CH; ++c) wnxt[c] = __ldg(&wp[c * 32 + lane]);
        }

        const float4* pp = s_pt[trow_cur & 1];

        float4 e[CH];
        float sum = 0.f, sq = 0.f;
        #pragma unroll
        for (int c = 0; c < CH; ++c) {
            const float4 q = pp[c * 32 + lane];   // LDS.128, conflict-free
            e[c].x = (float)wcur[c].x * ws + q.x;
            e[c].y = (float)wcur[c].y * ws + q.y;
            e[c].z = (float)wcur[c].z * ws + q.z;
            e[c].w = (float)wcur[c].w * ws + q.w;
            sum += e[c].x + e[c].y + e[c].z + e[c].w;
            sq  += e[c].x * e[c].x + e[c].y * e[c].y
                 + e[c].z * e[c].z + e[c].w * e[c].w;
        }

        // Pure warp reduction (full row lives in this warp). The next
        // token's LDGs are in flight underneath this chain.
        #pragma unroll
        for (int off = 16; off > 0; off >>= 1) {
            sum += __shfl_xor_sync(0xFFFFFFFFu, sum, off);
            sq  += __shfl_xor_sync(0xFFFFFFFFu, sq,  off);
        }

        const float inv_h = 1.0f / (float)H;
        const float mean  = sum * inv_h;
        float var = sq * inv_h - mean * mean;
        var = fmaxf(var, 0.0f);

        // The reference's 8-iteration Newton-Raphson sqrt converges to
        // sqrt(var) to full fp32 precision for this data's var range.
        const float std_approx = sqrtf(var);
        const float inv_std = __fdividef(1.0f, std_approx + 1e-12f);

        float4* orow = out + (size_t)token * VPR;
        #pragma unroll
        for (int c = 0; c < CH; ++c) {
            const int col = c * 32 + lane;
            const float4 g  = s_g[col];
            const float4 bb = s_b[col];
            float4 o;
            o.x = g.x * ((e[c].x - mean) * inv_std) + bb.x;
            o.y = g.y * ((e[c].y - mean) * inv_std) + bb.y;
            o.z = g.z * ((e[c].z - mean) * inv_std) + bb.z;
            o.w = g.w * ((e[c].w - mean) * inv_std) + bb.w;
            store_streaming(&orow[col], o);
        }

        if (have_next) {
            #pragma unroll
            for (int c = 0; c < CH; ++c) wcur[c] = wnxt[c];
            trow_cur = trow_nxt;
        }
    }
}

extern "C" void kernel_launch(void* const* d_in, const int* in_sizes, int n_in,
                              void* d_out, int out_size)
{
    const int*   input_ids      = (const int*)  d_in[0];
    const int*   token_type_ids = (const int*)  d_in[1];
    const int*   word_table     = (const int*)  d_in[2];
    const float* word_scale     = (const float*)d_in[3];
    const int*   pos_table      = (const int*)  d_in[4];
    const float* pos_scale      = (const float*)d_in[5];
    const int*   type_table     = (const int*)  d_in[6];
    const float* type_scale     = (const float*)d_in[7];
    const float* ln_w           = (const float*)d_in[8];
    const float* ln_b           = (const float*)d_in[9];

    const int n_tokens = in_sizes[0];       // B*S
    const int S        = in_sizes[4] / H;   // 512
    const int B        = n_tokens / S;      // 64

    const int bg   = (B + BPC - 1) / BPC;   // batch groups (4)
    const int grid = S * bg;                // 2048

    bert_emb_ln_kernel<<<grid, TPB>>>(
        input_ids, token_type_ids,
        (const int4*)word_table, word_scale,
        (const int4*)pos_table,  pos_scale,
        (const int4*)type_table, type_scale,
        (const float4*)ln_w, (const float4*)ln_b,
        (float4*)d_out, S, B);
}

// round 16
// speedup vs baseline: 1.4969x; 1.4969x over previous
#include <cuda_runtime.h>
#include <cstdint>

// INT8BertEmbeddings R16 = R13 (best: 32.8us) with TOKW 4->8 (BPC 16->32).
// R15's register prefetch regressed badly (61.5us) -- third failed
// latency-overlap scheme; the compiler-scheduled R13 loop is near its
// per-warp latency optimum. This round only halves the per-CTA smem-fill
// amortized cost (fill overhead ~10-13% of L1 work) by giving each CTA 32
// tokens instead of 16. grid = S * B/32 = 1024, still one full wave.
// Single kernel, s-major CTA mapping, pt+ln in smem.

constexpr int H    = 768;
constexpr int VPR  = H / 4;      // 192 float4/int4 per row
constexpr int TPB  = 128;        // 4 warps
constexpr int NW   = TPB / 32;
constexpr int TOKW = 8;          // batches per warp
constexpr int BPC  = NW * TOKW;  // 32 batches per CTA
constexpr int CH   = VPR / 32;   // 6 chunks per warp per row
constexpr int MAX_T = 2;

__device__ __forceinline__ void store_streaming(float4* addr, float4 v) {
    asm volatile("st.global.cs.v4.f32 [%0], {%1, %2, %3, %4};"
                 :: "l"(addr), "f"(v.x), "f"(v.y), "f"(v.z), "f"(v.w)
                 : "memory");
}

__global__ __launch_bounds__(TPB, 8) void bert_emb_ln_kernel(
    const int*  __restrict__ input_ids,
    const int*  __restrict__ token_type_ids,
    const int4* __restrict__ word_table,
    const float* __restrict__ word_scale,
    const int4* __restrict__ pos_table,
    const float* __restrict__ pos_scale,
    const int4* __restrict__ type_table,
    const float* __restrict__ type_scale,
    const float4* __restrict__ ln_w,
    const float4* __restrict__ ln_b,
    float4* __restrict__ out,
    int S, int B)
{
    const int tid  = threadIdx.x;
    const int lane = tid & 31;
    const int warp = tid >> 5;

    const int s  = blockIdx.x % S;           // sequence position for this CTA
    const int bg = blockIdx.x / S;           // batch group
    const int b0 = bg * BPC + warp * TOKW;   // first batch for this warp

    // smem: fused pos+type rows for this s (both type variants) + ln params.
    __shared__ __align__(16) float4 s_pt[MAX_T][VPR];
    __shared__ __align__(16) float4 s_g[VPR];
    __shared__ __align__(16) float4 s_b[VPR];

    {
        const float ps = __ldg(pos_scale);
        const float ts = __ldg(type_scale);
        #pragma unroll
        for (int c = 0; c < (VPR + TPB - 1) / TPB; ++c) {
            const int idx = c * TPB + tid;
            if (idx < VPR) {
                const int4 pr = __ldg(&pos_table[(size_t)s * VPR + idx]);
                const int4 t0 = __ldg(&type_table[idx]);
                const int4 t1 = __ldg(&type_table[VPR + idx]);
                const float px = (float)pr.x * ps, py = (float)pr.y * ps;
                const float pz = (float)pr.z * ps, pw = (float)pr.w * ps;
                s_pt[0][idx] = make_float4(px + (float)t0.x * ts, py + (float)t0.y * ts,
                                           pz + (float)t0.z * ts, pw + (float)t0.w * ts);
                s_pt[1][idx] = make_float4(px + (float)t1.x * ts, py + (float)t1.y * ts,
                                           pz + (float)t1.z * ts, pw + (float)t1.w * ts);
                s_g[idx] = __ldg(&ln_w[idx]);
                s_b[idx] = __ldg(&ln_b[idx]);
            }
        }
    }
    __syncthreads();   // uniform, once

    const float ws = __ldg(word_scale);

    #pragma unroll
    for (int i = 0; i < TOKW; ++i) {
        const int b = b0 + i;
        if (b >= B) return;
        const int token = b * S + s;

        const int wrow = __ldg(&input_ids[token]);
        const int trow = __ldg(&token_type_ids[token]);

        const int4*   wp = word_table + (size_t)wrow * VPR;
        const float4* pp = s_pt[trow & 1];

        float4 e[CH];
        float sum = 0.f, sq = 0.f;
        #pragma unroll
        for (int c = 0; c < CH; ++c) {
            const int col = c * 32 + lane;
            const int4   w = __ldg(&wp[col]);
            const float4 q = pp[col];       // LDS.128, conflict-free
            e[c].x = (float)w.x * ws + q.x;
            e[c].y = (float)w.y * ws + q.y;
            e[c].z = (float)w.z * ws + q.z;
            e[c].w = (float)w.w * ws + q.w;
            sum += e[c].x + e[c].y + e[c].z + e[c].w;
            sq  += e[c].x * e[c].x + e[c].y * e[c].y
                 + e[c].z * e[c].z + e[c].w * e[c].w;
        }

        // Pure warp reduction (full row lives in this warp).
        #pragma unroll
        for (int off = 16; off > 0; off >>= 1) {
            sum += __shfl_xor_sync(0xFFFFFFFFu, sum, off);
            sq  += __shfl_xor_sync(0xFFFFFFFFu, sq,  off);
        }

        const float inv_h = 1.0f / (float)H;
        const float mean  = sum * inv_h;
        float var = sq * inv_h - mean * mean;
        var = fmaxf(var, 0.0f);

        // The reference's 8-iteration Newton-Raphson sqrt converges to
        // sqrt(var) to full fp32 precision for this data's var range.
        const float std_approx = sqrtf(var);
        const float inv_std = __fdividef(1.0f, std_approx + 1e-12f);

        float4* orow = out + (size_t)token * VPR;
        #pragma unroll
        for (int c = 0; c < CH; ++c) {
            const int col = c * 32 + lane;
            const float4 g  = s_g[col];
            const float4 bb = s_b[col];
            float4 o;
            o.x = g.x * ((e[c].x - mean) * inv_std) + bb.x;
            o.y = g.y * ((e[c].y - mean) * inv_std) + bb.y;
            o.z = g.z * ((e[c].z - mean) * inv_std) + bb.z;
            o.w = g.w * ((e[c].w - mean) * inv_std) + bb.w;
            store_streaming(&orow[col], o);
        }
    }
}

extern "C" void kernel_launch(void* const* d_in, const int* in_sizes, int n_in,
                              void* d_out, int out_size)
{
    const int*   input_ids      = (const int*)  d_in[0];
    const int*   token_type_ids = (const int*)  d_in[1];
    const int*   word_table     = (const int*)  d_in[2];
    const float* word_scale     = (const float*)d_in[3];
    const int*   pos_table      = (const int*)  d_in[4];
    const float* pos_scale      = (const float*)d_in[5];
    const int*   type_table     = (const int*)  d_in[6];
    const float* type_scale     = (const float*)d_in[7];
    const float* ln_w           = (const float*)d_in[8];
    const float* ln_b           = (const float*)d_in[9];

    const int n_tokens = in_sizes[0];       // B*S
    const int S        = in_sizes[4] / H;   // 512
    const int B        = n_tokens / S;      // 64

    const int bg   = (B + BPC - 1) / BPC;   // batch groups (2)
    const int grid = S * bg;                // 1024

    bert_emb_ln_kernel<<<grid, TPB>>>(
        input_ids, token_type_ids,
        (const int4*)word_table, word_scale,
        (const int4*)pos_table,  pos_scale,
        (const int4*)type_table, type_scale,
        (const float4*)ln_w, (const float4*)ln_b,
        (float4*)d_out, S, B);
}

// round 17
// speedup vs baseline: 1.8340x; 1.2252x over previous
#include <cuda_runtime.h>
#include <cstdint>

// INT8BertEmbeddings R17 = R13 inner loop (best) with TPB 128->256.
// R16 (TOKW=8) regressed because it halved total warp parallelism (8192->
// 4096 warps). R17 keeps TOKW=4 and 8192 warps, but packs 8 warps per CTA
// (BPC=32, grid=1024): the per-CTA smem fill (pos+type dequant + ln params)
// now amortizes over 32 tokens instead of 16, with the inner loop unchanged.
// Occupancy identical to R13: 64 regs x 256 thr -> 4 CTAs/SM = 32 warps/SM.

constexpr int H    = 768;
constexpr int VPR  = H / 4;      // 192 float4/int4 per row
constexpr int TPB  = 256;        // 8 warps
constexpr int NW   = TPB / 32;
constexpr int TOKW = 4;          // batches per warp (same as R13)
constexpr int BPC  = NW * TOKW;  // 32 batches per CTA
constexpr int CH   = VPR / 32;   // 6 chunks per warp per row
constexpr int MAX_T = 2;

__device__ __forceinline__ void store_streaming(float4* addr, float4 v) {
    asm volatile("st.global.cs.v4.f32 [%0], {%1, %2, %3, %4};"
                 :: "l"(addr), "f"(v.x), "f"(v.y), "f"(v.z), "f"(v.w)
                 : "memory");
}

__global__ __launch_bounds__(TPB, 4) void bert_emb_ln_kernel(
    const int*  __restrict__ input_ids,
    const int*  __restrict__ token_type_ids,
    const int4* __restrict__ word_table,
    const float* __restrict__ word_scale,
    const int4* __restrict__ pos_table,
    const float* __restrict__ pos_scale,
    const int4* __restrict__ type_table,
    const float* __restrict__ type_scale,
    const float4* __restrict__ ln_w,
    const float4* __restrict__ ln_b,
    float4* __restrict__ out,
    int S, int B)
{
    const int tid  = threadIdx.x;
    const int lane = tid & 31;
    const int warp = tid >> 5;

    const int s  = blockIdx.x % S;           // sequence position for this CTA
    const int bg = blockIdx.x / S;           // batch group
    const int b0 = bg * BPC + warp * TOKW;   // first batch for this warp

    // smem: fused pos+type rows for this s (both type variants) + ln params.
    __shared__ __align__(16) float4 s_pt[MAX_T][VPR];
    __shared__ __align__(16) float4 s_g[VPR];
    __shared__ __align__(16) float4 s_b[VPR];

    {
        const float ps = __ldg(pos_scale);
        const float ts = __ldg(type_scale);
        if (tid < VPR) {
            const int idx = tid;
            const int4 pr = __ldg(&pos_table[(size_t)s * VPR + idx]);
            const int4 t0 = __ldg(&type_table[idx]);
            const int4 t1 = __ldg(&type_table[VPR + idx]);
            const float px = (float)pr.x * ps, py = (float)pr.y * ps;
            const float pz = (float)pr.z * ps, pw = (float)pr.w * ps;
            s_pt[0][idx] = make_float4(px + (float)t0.x * ts, py + (float)t0.y * ts,
                                       pz + (float)t0.z * ts, pw + (float)t0.w * ts);
            s_pt[1][idx] = make_float4(px + (float)t1.x * ts, py + (float)t1.y * ts,
                                       pz + (float)t1.z * ts, pw + (float)t1.w * ts);
        } else {
            const int idx = tid - VPR;       // 0..63: covers first part of ln
            s_g[idx] = __ldg(&ln_w[idx]);
            s_b[idx] = __ldg(&ln_b[idx]);
        }
        // remaining ln entries (64..191) loaded by all threads' second step
        const int idx2 = tid + (TPB - VPR);  // 64..319
        if (tid < VPR && idx2 >= TPB - VPR && idx2 - (TPB - VPR) < VPR - (TPB - VPR)) {
            // covered below instead
        }
    }
    // Simpler, uniform second fill pass for ln params (idx 64..191 by
    // threads 64..191; idx 0..63 already done by threads 192..255).
    if (tid >= TPB - VPR && tid < TPB - VPR + (VPR - (TPB - VPR))) {
        const int idx = tid;                 // 64..191 map directly
        if (idx < VPR) {
            s_g[idx] = __ldg(&ln_w[idx]);
            s_b[idx] = __ldg(&ln_b[idx]);
        }
    }
    __syncthreads();   // uniform, once

    const float ws = __ldg(word_scale);

    #pragma unroll
    for (int i = 0; i < TOKW; ++i) {
        const int b = b0 + i;
        if (b >= B) return;
        const int token = b * S + s;

        const int wrow = __ldg(&input_ids[token]);
        const int trow = __ldg(&token_type_ids[token]);

        const int4*   wp = word_table + (size_t)wrow * VPR;
        const float4* pp = s_pt[trow & 1];

        float4 e[CH];
        float sum = 0.f, sq = 0.f;
        #pragma unroll
        for (int c = 0; c < CH; ++c) {
            const int col = c * 32 + lane;
            const int4   w = __ldg(&wp[col]);
            const float4 q = pp[col];       // LDS.128, conflict-free
            e[c].x = (float)w.x * ws + q.x;
            e[c].y = (float)w.y * ws + q.y;
            e[c].z = (float)w.z * ws + q.z;
            e[c].w = (float)w.w * ws + q.w;
            sum += e[c].x + e[c].y + e[c].z + e[c].w;
            sq  += e[c].x * e[c].x + e[c].y * e[c].y
                 + e[c].z * e[c].z + e[c].w * e[c].w;
        }

        // Pure warp reduction (full row lives in this warp).
        #pragma unroll
        for (int off = 16; off > 0; off >>= 1) {
            sum += __shfl_xor_sync(0xFFFFFFFFu, sum, off);
            sq  += __shfl_xor_sync(0xFFFFFFFFu, sq,  off);
        }

        const float inv_h = 1.0f / (float)H;
        const float mean  = sum * inv_h;
        float var = sq * inv_h - mean * mean;
        var = fmaxf(var, 0.0f);

        // The reference's 8-iteration Newton-Raphson sqrt converges to
        // sqrt(var) to full fp32 precision for this data's var range.
        const float std_approx = sqrtf(var);
        const float inv_std = __fdividef(1.0f, std_approx + 1e-12f);

        float4* orow = out + (size_t)token * VPR;
        #pragma unroll
        for (int c = 0; c < CH; ++c) {
            const int col = c * 32 + lane;
            const float4 g  = s_g[col];
            const float4 bb = s_b[col];
            float4 o;
            o.x = g.x * ((e[c].x - mean) * inv_std) + bb.x;
            o.y = g.y * ((e[c].y - mean) * inv_std) + bb.y;
            o.z = g.z * ((e[c].z - mean) * inv_std) + bb.z;
            o.w = g.w * ((e[c].w - mean) * inv_std) + bb.w;
            store_streaming(&orow[col], o);
        }
    }
}

extern "C" void kernel_launch(void* const* d_in, const int* in_sizes, int n_in,
                              void* d_out, int out_size)
{
    const int*   input_ids      = (const int*)  d_in[0];
    const int*   token_type_ids = (const int*)  d_in[1];
    const int*   word_table     = (const int*)  d_in[2];
    const float* word_scale     = (const float*)d_in[3];
    const int*   pos_table      = (const int*)  d_in[4];
    const float* pos_scale      = (const float*)d_in[5];
    const int*   type_table     = (const int*)  d_in[6];
    const float* type_scale     = (const float*)d_in[7];
    const float* ln_w           = (const float*)d_in[8];
    const float* ln_b           = (const float*)d_in[9];

    const int n_tokens = in_sizes[0];       // B*S
    const int S        = in_sizes[4] / H;   // 512
    const int B        = n_tokens / S;      // 64

    const int bg   = (B + BPC - 1) / BPC;   // batch groups (2)
    const int grid = S * bg;                // 1024

    bert_emb_ln_kernel<<<grid, TPB>>>(
        input_ids, token_type_ids,
        (const int4*)word_table, word_scale,
        (const int4*)pos_table,  pos_scale,
        (const int4*)type_table, type_scale,
        (const float4*)ln_w, (const float4*)ln_b,
        (float4*)d_out, S, B);
}